// round 14
// baseline (speedup 1.0000x reference)
#include <cuda_runtime.h>
#include <math.h>

#define Bb 32
#define Ss 64
#define Hh 300
#define HPAD 304
#define HP2 320
#define Ll 20
#define KC 16
#define KH 32
#define CH 160
#define PSIDE (Bb*Ss*CH)
#define EPSV 1e-8f
#define AVP 72   // attvec smem pitch (floats): 288B rows, 16B-aligned

typedef unsigned long long ull;

__device__ __forceinline__ void fma2(ull &d, ull a, ull b) {
    asm("fma.rn.f32x2 %0, %1, %2, %0;" : "+l"(d) : "l"(a), "l"(b));
}
__device__ __forceinline__ void mul2(ull &d, ull a, ull b) {
    asm("mul.rn.f32x2 %0, %1, %2;" : "=l"(d) : "l"(a), "l"(b));
}
__device__ __forceinline__ void add2(ull &d, ull a) {
    asm("add.rn.f32x2 %0, %0, %1;" : "+l"(d) : "l"(a));
}
__device__ __forceinline__ ull pk2(float x) {
    ull r; asm("mov.b64 %0, {%1, %1};" : "=l"(r) : "f"(x)); return r;
}
__device__ __forceinline__ float2 upk(ull v) {
    float2 r; asm("mov.b64 {%0, %1}, %2;" : "=f"(r.x), "=f"(r.y) : "l"(v)); return r;
}

// ---------------- scratch ----------------
__device__ float g_cos [2*Bb*Ss*Ss];
__device__ float g_rsum[2*Bb*Ss];
__device__ float g_csum[2*Bb*Ss];
__device__ float g_pvm [2*Bb*Ss*Hh];
__device__ float g_pvx [2*Bb*Ss*Hh];
__device__ float g_qvm [2*Bb*Ss*Hh];
__device__ float g_qvx [2*Bb*Ss*Hh];
__device__ float g_w2t [8*HP2*Ll];      // [wi][h][l], squared, zero-padded

// =========================================================================
// K0: transpose + square W -> g_w2t[wi][h][l]
// =========================================================================
__global__ void w2prep_kernel(const float* __restrict__ W)
{
    int idx = blockIdx.x * 256 + threadIdx.x;
    if (idx >= 8*HP2*Ll) return;
    int wi = idx / (HP2*Ll);
    int rem = idx - wi*(HP2*Ll);
    int h = rem / Ll, l = rem - h*Ll;
    float w = (h < Hh) ? W[(wi*Ll + l)*Hh + h] : 0.f;
    g_w2t[idx] = w * w;
}

// =========================================================================
// K1: unweighted cosine per (b,dir). 256 thr, 4x4 tile, FFMA2 inner loop.
// =========================================================================
__global__ void __launch_bounds__(256) attcos_kernel(const float* __restrict__ p,
                                                     const float* __restrict__ q)
{
    int bd = blockIdx.x;
    int d  = bd >> 5, b = bd & 31;
    int t  = threadIdx.x;
    int tr = t >> 4, tc = t & 15;
    int row_s = t >> 2, hq = t & 3;

    __shared__ __align__(16) float As[KC][64];
    __shared__ __align__(16) float Bs[KC][64];
    __shared__ float snorm[2][4][64];
    __shared__ float rn[2][64];
    __shared__ float red[16][64];

    const float* Pb = p + b*Ss*600 + d*Hh;
    const float* Qb = q + b*Ss*600 + d*Hh;

    ull acc2[4][2];
#pragma unroll
    for (int i = 0; i < 4; i++) { acc2[i][0] = 0ull; acc2[i][1] = 0ull; }
    float np2 = 0.f, nq2 = 0.f;

    for (int h0 = 0; h0 < HPAD; h0 += KC) {
        int h = h0 + hq*4;
        float4 pv, qv;
        if (h + 3 < Hh) {
            pv = *(const float4*)(Pb + row_s*600 + h);
            qv = *(const float4*)(Qb + row_s*600 + h);
        } else {
            float* pp = (float*)&pv; float* qq = (float*)&qv;
#pragma unroll
            for (int i = 0; i < 4; i++) {
                bool in = (h + i < Hh);
                pp[i] = in ? Pb[row_s*600 + h + i] : 0.f;
                qq[i] = in ? Qb[row_s*600 + h + i] : 0.f;
            }
        }
        As[hq*4+0][row_s] = pv.x; As[hq*4+1][row_s] = pv.y;
        As[hq*4+2][row_s] = pv.z; As[hq*4+3][row_s] = pv.w;
        Bs[hq*4+0][row_s] = qv.x; Bs[hq*4+1][row_s] = qv.y;
        Bs[hq*4+2][row_s] = qv.z; Bs[hq*4+3][row_s] = qv.w;
        np2 += pv.x*pv.x + pv.y*pv.y + pv.z*pv.z + pv.w*pv.w;
        nq2 += qv.x*qv.x + qv.y*qv.y + qv.z*qv.z + qv.w*qv.w;
        __syncthreads();
#pragma unroll
        for (int k = 0; k < KC; k++) {
            float4 a = *(const float4*)(&As[k][tr*4]);
            ulonglong2 bq = *(const ulonglong2*)(&Bs[k][tc*4]);
            ull a0 = pk2(a.x), a1 = pk2(a.y), a2 = pk2(a.z), a3 = pk2(a.w);
            fma2(acc2[0][0], a0, bq.x); fma2(acc2[0][1], a0, bq.y);
            fma2(acc2[1][0], a1, bq.x); fma2(acc2[1][1], a1, bq.y);
            fma2(acc2[2][0], a2, bq.x); fma2(acc2[2][1], a2, bq.y);
            fma2(acc2[3][0], a3, bq.x); fma2(acc2[3][1], a3, bq.y);
        }
        __syncthreads();
    }

    snorm[0][hq][row_s] = np2;
    snorm[1][hq][row_s] = nq2;
    __syncthreads();
    if (t < 64) {
        rn[0][t] = 1.f / sqrtf(snorm[0][0][t] + snorm[0][1][t] + snorm[0][2][t] + snorm[0][3][t]);
        rn[1][t] = 1.f / sqrtf(snorm[1][0][t] + snorm[1][1][t] + snorm[1][2][t] + snorm[1][3][t]);
    }
    __syncthreads();

    float rp[4], rq[4];
#pragma unroll
    for (int i = 0; i < 4; i++) rp[i] = rn[0][tr*4+i];
#pragma unroll
    for (int j = 0; j < 4; j++) rq[j] = rn[1][tc*4+j];

    float* gc = g_cos + bd*(Ss*Ss);
    float rowsum[4], colsum[4];
#pragma unroll
    for (int i = 0; i < 4; i++) rowsum[i] = 0.f;
#pragma unroll
    for (int j = 0; j < 4; j++) colsum[j] = 0.f;

#pragma unroll
    for (int i = 0; i < 4; i++) {
        float2 c0 = upk(acc2[i][0]);
        float2 c1 = upk(acc2[i][1]);
        float c[4] = {c0.x, c0.y, c1.x, c1.y};
#pragma unroll
        for (int j = 0; j < 4; j++) {
            c[j] *= rp[i] * rq[j];
            rowsum[i] += c[j];
            colsum[j] += c[j];
        }
        *(float4*)(gc + (tr*4+i)*64 + tc*4) = make_float4(c[0], c[1], c[2], c[3]);
    }

#pragma unroll
    for (int i = 0; i < 4; i++) red[tc][tr*4+i] = rowsum[i];
    __syncthreads();
    if (t < 64) {
        float s = 0.f;
#pragma unroll
        for (int g = 0; g < 16; g++) s += red[g][t];
        g_rsum[bd*Ss + t] = s;
    }
    __syncthreads();
#pragma unroll
    for (int j = 0; j < 4; j++) red[tr][tc*4+j] = colsum[j];
    __syncthreads();
    if (t < 64) {
        float s = 0.f;
#pragma unroll
        for (int g = 0; g < 16; g++) s += red[g][t];
        g_csum[bd*Ss + t] = s;
    }
}

// =========================================================================
// K2: attentive vectors (mean + max fused), packed f32x2 mul/add.
// __launch_bounds__(256,4): cap regs at 64.
// =========================================================================
__global__ void __launch_bounds__(256, 4) attvec_kernel(const float* __restrict__ p,
                                                        const float* __restrict__ q)
{
    int bd   = blockIdx.x;
    int d    = bd >> 5, b = bd & 31;
    int h0   = blockIdx.y * 64;
    int side = blockIdx.z;
    int t    = threadIdx.x;
    int ty   = t >> 4, tx = t & 15;

    __shared__ __align__(16) float As[64][AVP];
    __shared__ __align__(16) float Bs[64][AVP];

    const float* gc = g_cos + bd*(Ss*Ss);
    const float* M  = (side ? q : p) + b*Ss*600 + d*Hh;

    for (int idx = t; idx < 4096; idx += 256) {
        int row = idx >> 6, col = idx & 63;
        float cv = gc[row*64 + col];              // always coalesced
        if (side) As[col][row] = cv;              // transposed write
        else      As[row][col] = cv;
        int h = h0 + col;
        Bs[row][col] = (h < Hh) ? M[row*600 + h] : 0.f;
    }
    __syncthreads();

    ull accM2[4][2];
    float accX[4][4];
#pragma unroll
    for (int i = 0; i < 4; i++) {
        accM2[i][0] = 0ull; accM2[i][1] = 0ull;
#pragma unroll
        for (int j = 0; j < 4; j++) accX[i][j] = -INFINITY;
    }

    for (int k = 0; k < 64; k++) {
        float4 a = *(const float4*)(&As[k][ty*4]);
        ulonglong2 bq = *(const ulonglong2*)(&Bs[k][tx*4]);
        ull a2[4] = {pk2(a.x), pk2(a.y), pk2(a.z), pk2(a.w)};
#pragma unroll
        for (int i = 0; i < 4; i++) {
            ull pr0, pr1;
            mul2(pr0, a2[i], bq.x);
            mul2(pr1, a2[i], bq.y);
            add2(accM2[i][0], pr0);
            add2(accM2[i][1], pr1);
            float2 f0 = upk(pr0), f1 = upk(pr1);
            accX[i][0] = fmaxf(accX[i][0], f0.x);
            accX[i][1] = fmaxf(accX[i][1], f0.y);
            accX[i][2] = fmaxf(accX[i][2], f1.x);
            accX[i][3] = fmaxf(accX[i][3], f1.y);
        }
    }

    float* vm = (side ? g_qvm : g_pvm) + bd*Ss*Hh;
    float* vx = (side ? g_qvx : g_pvx) + bd*Ss*Hh;
    const float* den = (side ? g_rsum : g_csum) + bd*Ss;

#pragma unroll
    for (int i = 0; i < 4; i++) {
        int r = ty*4 + i;
        float dn = den[r];
        float2 m0 = upk(accM2[i][0]);
        float2 m1 = upk(accM2[i][1]);
        float mv[4] = {m0.x, m0.y, m1.x, m1.y};
#pragma unroll
        for (int j = 0; j < 4; j++) {
            int h = h0 + tx*4 + j;
            if (h < Hh) {
                vm[r*Hh + h] = mv[j] / dn;
                vx[r*Hh + h] = accX[i][j];
            }
        }
    }
}

// =========================================================================
// K3: maxpool, 2 l per block, 256 thr (16x16 grid, 4 rows x 4 cols per l).
// Halved accumulator regs vs 128-thr version -> ~24 warps/SM.
// Software-pipelined staging; A pre-packed f32x2; FFMA2 inner loop.
// =========================================================================
__global__ void __launch_bounds__(256) maxpool_kernel(const float* __restrict__ p,
                                                      const float* __restrict__ q,
                                                      const float* __restrict__ W,
                                                      float* __restrict__ out)
{
    int lp = blockIdx.x;                // l pair: l = lp*2 + {0,1}
    int b  = blockIdx.y, d = blockIdx.z;
    int t  = threadIdx.x;
    int tr = t >> 4;                    // 0..15 -> rows tr*4..tr*4+3
    int tc = t & 15;                    // 0..15 -> cols tc*4..tc*4+3
    int row_s = t >> 2, hq = t & 3;     // staging: row 0..63, float4 segment 0..3

    __shared__ __align__(16) ull   Ap[KC][64];
    __shared__ __align__(16) float Bs[2][KC][64];
    __shared__ float ws2[2][HPAD];
    __shared__ float snorm[2][2][4][64];   // [l][p/q][hq][row]
    __shared__ float rn[2][2][64];         // [l][p/q][row]
    __shared__ float red[16][64];

    const float* w0r = W + ((2 + d)*Ll + lp*2 + 0)*Hh;
    const float* w1r = W + ((2 + d)*Ll + lp*2 + 1)*Hh;
    for (int h = t; h < HPAD; h += 256) {
        float a = (h < Hh) ? w0r[h] : 0.f;
        float c = (h < Hh) ? w1r[h] : 0.f;
        ws2[0][h] = a * a;
        ws2[1][h] = c * c;
    }

    const float* Pb = p + b*Ss*600 + d*Hh;
    const float* Qb = q + b*Ss*600 + d*Hh;

    float pv[4], qv[4];
    auto load_tile = [&](int h0n) {
        int h = h0n + hq*4;
        float4 pvv, qvv;
        if (h + 3 < Hh) {
            pvv = *(const float4*)(Pb + row_s*600 + h);
            qvv = *(const float4*)(Qb + row_s*600 + h);
        } else {
            float* pp = (float*)&pvv; float* qq = (float*)&qvv;
#pragma unroll
            for (int i = 0; i < 4; i++) {
                bool in = (h + i < Hh);
                pp[i] = in ? Pb[row_s*600 + h + i] : 0.f;
                qq[i] = in ? Qb[row_s*600 + h + i] : 0.f;
            }
        }
        pv[0] = pvv.x; pv[1] = pvv.y; pv[2] = pvv.z; pv[3] = pvv.w;
        qv[0] = qvv.x; qv[1] = qvv.y; qv[2] = qvv.z; qv[3] = qvv.w;
    };

    load_tile(0);                   // prefetch tile 0 (overlaps ws2 staging)
    __syncthreads();                // ws2 ready

    ull acc2[2][4][2];              // [l][row i][ull col pair]
#pragma unroll
    for (int l = 0; l < 2; l++)
#pragma unroll
        for (int i = 0; i < 4; i++) { acc2[l][i][0] = 0ull; acc2[l][i][1] = 0ull; }
    float np2[2] = {0.f, 0.f}, nq2[2] = {0.f, 0.f};

    for (int h0 = 0; h0 < HPAD; h0 += KC) {
        int hb = h0 + hq*4;
#pragma unroll
        for (int j = 0; j < 4; j++) {
            int kk = hq*4 + j;
            Ap[kk][row_s] = pk2(pv[j]);
            float pj = pv[j], qj = qv[j];
            float wa = ws2[0][hb + j], wb = ws2[1][hb + j];
            Bs[0][kk][row_s] = qj * wa;
            Bs[1][kk][row_s] = qj * wb;
            np2[0] += pj*pj*wa;  np2[1] += pj*pj*wb;
            nq2[0] += qj*qj*wa;  nq2[1] += qj*qj*wb;
        }
        __syncthreads();            // smem ready
        if (h0 + KC < HPAD) load_tile(h0 + KC);   // prefetch next tile
#pragma unroll
        for (int k = 0; k < KC; k++) {
            ulonglong2 a01 = *(const ulonglong2*)(&Ap[k][tr*4+0]);
            ulonglong2 a23 = *(const ulonglong2*)(&Ap[k][tr*4+2]);
            ull av2[4] = {a01.x, a01.y, a23.x, a23.y};
            ulonglong2 b0 = *(const ulonglong2*)(&Bs[0][k][tc*4]);
            ulonglong2 b1 = *(const ulonglong2*)(&Bs[1][k][tc*4]);
#pragma unroll
            for (int i = 0; i < 4; i++) {
                fma2(acc2[0][i][0], av2[i], b0.x);
                fma2(acc2[0][i][1], av2[i], b0.y);
                fma2(acc2[1][i][0], av2[i], b1.x);
                fma2(acc2[1][i][1], av2[i], b1.y);
            }
        }
        __syncthreads();            // smem consumed
    }

#pragma unroll
    for (int l = 0; l < 2; l++) {
        snorm[l][0][hq][row_s] = np2[l];
        snorm[l][1][hq][row_s] = nq2[l];
    }
    __syncthreads();
    if (t < 64) {
#pragma unroll
        for (int l = 0; l < 2; l++) {
            rn[l][0][t] = sqrtf(snorm[l][0][0][t] + snorm[l][0][1][t] + snorm[l][0][2][t] + snorm[l][0][3][t]);
            rn[l][1][t] = sqrtf(snorm[l][1][0][t] + snorm[l][1][1][t] + snorm[l][1][2][t] + snorm[l][1][3][t]);
        }
    }
    __syncthreads();

#pragma unroll
    for (int l = 0; l < 2; l++) {
        float npv[4], nqv[4], rmax[4], cmax[4];
#pragma unroll
        for (int i = 0; i < 4; i++) { npv[i] = rn[l][0][tr*4+i]; rmax[i] = -INFINITY; }
#pragma unroll
        for (int j = 0; j < 4; j++) { nqv[j] = rn[l][1][tc*4+j]; cmax[j] = -INFINITY; }

#pragma unroll
        for (int i = 0; i < 4; i++) {
            float2 c0 = upk(acc2[l][i][0]);
            float2 c1 = upk(acc2[l][i][1]);
            float cf[4] = {c0.x, c0.y, c1.x, c1.y};
#pragma unroll
            for (int j = 0; j < 4; j++) {
                float c = cf[j] / fmaxf(npv[i]*nqv[j], EPSV);
                rmax[i] = fmaxf(rmax[i], c);
                cmax[j] = fmaxf(cmax[j], c);
            }
        }

        int ch = (2 + d)*Ll + lp*2 + l;
        // row max over sq (16 tc groups) -> mv_p[sp]
#pragma unroll
        for (int i = 0; i < 4; i++) red[tc][tr*4+i] = rmax[i];
        __syncthreads();
        if (t < 64) {
            float m = -INFINITY;
#pragma unroll
            for (int g = 0; g < 16; g++) m = fmaxf(m, red[g][t]);
            out[(b*Ss + t)*CH + ch] = m;
        }
        __syncthreads();
        // col max over sp (16 tr groups) -> mv_q[sq]
#pragma unroll
        for (int j = 0; j < 4; j++) red[tr][tc*4+j] = cmax[j];
        __syncthreads();
        if (t < 64) {
            float m = -INFINITY;
#pragma unroll
            for (int g = 0; g < 16; g++) m = fmaxf(m, red[g][t]);
            out[PSIDE + (b*Ss + t)*CH + ch] = m;
        }
        __syncthreads();
    }
}

// =========================================================================
// K4: mp_cos epilogue. Block = (b, s-half, dir, side): 256 blocks, 160 thr.
// =========================================================================
__global__ void __launch_bounds__(160) mpcos_kernel(const float* __restrict__ p,
                                                    const float* __restrict__ q,
                                                    float* __restrict__ out)
{
    int b    = blockIdx.x >> 1;
    int sh   = blockIdx.x & 1;
    int dir  = blockIdx.y;
    int side = blockIdx.z;
    int t    = threadIdx.x;
    int s    = t & 31;
    int lg   = t >> 5;
    int l0   = lg * 4;
    int bd   = dir*Bb + b;
    int sg   = sh*32 + s;

    __shared__ float xt [KH][33];
    __shared__ float ymt[KH][33];
    __shared__ float yxt[KH][33];
    __shared__ float yfs[KH];
    __shared__ __align__(16) float w2s[3][KH][20];

    const float* Xb  = (side ? q : p) + (b*Ss + sh*32)*600 + dir*Hh;
    const float* Yfb = (side ? p : q) + (b*Ss + (dir ? 0 : (Ss-1)))*600 + dir*Hh;
    const float* Ymb = (side ? g_pvm : g_qvm) + (bd*Ss + sh*32)*Hh;
    const float* Yxb = (side ? g_pvx : g_qvx) + (bd*Ss + sh*32)*Hh;
    const int wi0 = dir, wi1 = 4 + dir, wi2 = 6 + dir;

    ull aF[2][3], aM[2][3], aX[2][3];
#pragma unroll
    for (int pr = 0; pr < 2; pr++)
#pragma unroll
        for (int m = 0; m < 3; m++) { aF[pr][m] = 0ull; aM[pr][m] = 0ull; aX[pr][m] = 0ull; }

    for (int h0 = 0; h0 < HP2; h0 += KH) {
        for (int idx = t; idx < 256; idx += 160) {
            int s_ = idx >> 3, qd = idx & 7;
            int h = h0 + qd*4;
            float4 xv, mv, vv;
            if (h + 3 < Hh) {
                xv = *(const float4*)(Xb  + s_*600 + h);
                mv = *(const float4*)(Ymb + s_*Hh  + h);
                vv = *(const float4*)(Yxb + s_*Hh  + h);
            } else {
                float* xp = (float*)&xv; float* mp2 = (float*)&mv; float* vp = (float*)&vv;
#pragma unroll
                for (int i = 0; i < 4; i++) {
                    bool in = (h + i < Hh);
                    xp[i]  = in ? Xb [s_*600 + h + i] : 0.f;
                    mp2[i] = in ? Ymb[s_*Hh  + h + i] : 0.f;
                    vp[i]  = in ? Yxb[s_*Hh  + h + i] : 0.f;
                }
            }
            float* xp = (float*)&xv; float* mp2 = (float*)&mv; float* vp = (float*)&vv;
#pragma unroll
            for (int i = 0; i < 4; i++) {
                xt [qd*4+i][s_] = xp[i];
                ymt[qd*4+i][s_] = mp2[i];
                yxt[qd*4+i][s_] = vp[i];
            }
        }
        if (t < KH) {
            int h = h0 + t;
            yfs[t] = (h < Hh) ? Yfb[h] : 0.f;
        }
        for (int idx = t; idx < 480; idx += 160) {
            int stg = idx / 160;
            int rem = idx - stg*160;
            int kk = rem / 5, lq2 = rem - kk*5;
            int wi = (stg == 0) ? wi0 : (stg == 1 ? wi1 : wi2);
            float4 wv = *(const float4*)(g_w2t + (wi*HP2 + h0 + kk)*Ll + lq2*4);
            *(float4*)(&w2s[stg][kk][lq2*4]) = wv;
        }
        __syncthreads();

#pragma unroll
        for (int kk = 0; kk < KH; kk++) {
            float x   = xt [kk][s];
            float ymv = ymt[kk][s];
            float yxv = yxt[kk][s];
            float yfv = yfs[kk];

            ull XX = pk2(x*x);
            ull PF = pk2(x*yfv);
            ull F2 = pk2(yfv*yfv);
            ull PM = pk2(x*ymv);
            ull M2 = pk2(ymv*ymv);
            ull PX = pk2(x*yxv);
            ull X2 = pk2(yxv*yxv);

            const ull* wf = (const ull*)&w2s[0][kk][l0];
            const ull* wm = (const ull*)&w2s[1][kk][l0];
            const ull* wx = (const ull*)&w2s[2][kk][l0];
#pragma unroll
            for (int pr = 0; pr < 2; pr++) {
                ull wfp = wf[pr], wmp = wm[pr], wxp = wx[pr];
                fma2(aF[pr][0], XX, wfp); fma2(aF[pr][1], PF, wfp); fma2(aF[pr][2], F2, wfp);
                fma2(aM[pr][0], XX, wmp); fma2(aM[pr][1], PM, wmp); fma2(aM[pr][2], M2, wmp);
                fma2(aX[pr][0], XX, wxp); fma2(aX[pr][1], PX, wxp); fma2(aX[pr][2], X2, wxp);
            }
        }
        __syncthreads();
    }

    float* ob = out + side*PSIDE + (b*Ss + sg)*CH;
#pragma unroll
    for (int pr = 0; pr < 2; pr++) {
        float2 nxF = upk(aF[pr][0]), numF = upk(aF[pr][1]), nyF = upk(aF[pr][2]);
        float2 nxM = upk(aM[pr][0]), numM = upk(aM[pr][1]), nyM = upk(aM[pr][2]);
        float2 nxX = upk(aX[pr][0]), numX = upk(aX[pr][1]), nyX = upk(aX[pr][2]);
#pragma unroll
        for (int hl = 0; hl < 2; hl++) {
            int l = l0 + pr*2 + hl;
            float nxf = hl ? nxF.y : nxF.x, nuf = hl ? numF.y : numF.x, nyf = hl ? nyF.y : nyF.x;
            float nxm = hl ? nxM.y : nxM.x, num = hl ? numM.y : numM.x, nym = hl ? nyM.y : nyM.x;
            float nxx = hl ? nxX.y : nxX.x, nux = hl ? numX.y : numX.x, nyx = hl ? nyX.y : nyX.x;
            ob[  0 + dir*Ll + l] = nuf / fmaxf(sqrtf(nxf)*sqrtf(nyf), EPSV);
            ob[ 80 + dir*Ll + l] = num / fmaxf(sqrtf(nxm)*sqrtf(nym), EPSV);
            ob[120 + dir*Ll + l] = nux / fmaxf(sqrtf(nxx)*sqrtf(nyx), EPSV);
        }
    }
}

// =========================================================================
// Fork/join plumbing (static-init; no device allocations afterwards).
// =========================================================================
struct HxCtx {
    cudaStream_t side;
    cudaEvent_t  eA, eB;
    bool ok;
    HxCtx() : ok(false) {
        if (cudaStreamCreateWithFlags(&side, cudaStreamNonBlocking) != cudaSuccess) return;
        if (cudaEventCreateWithFlags(&eA, cudaEventDisableTiming) != cudaSuccess) return;
        if (cudaEventCreateWithFlags(&eB, cudaEventDisableTiming) != cudaSuccess) return;
        ok = true;
    }
};
static HxCtx g_hx;

extern "C" void kernel_launch(void* const* d_in, const int* in_sizes, int n_in,
                              void* d_out, int out_size) {
    const float* p = (const float*)d_in[0];
    const float* q = (const float*)d_in[1];
    const float* W = (const float*)d_in[2];
    float* out = (float*)d_out;

    if (g_hx.ok) {
        // fork: maxpool on side stream, independent of the attentive chain
        cudaEventRecord(g_hx.eA, 0);
        cudaStreamWaitEvent(g_hx.side, g_hx.eA, 0);
        maxpool_kernel<<<dim3(Ll/2, Bb, 2), 256, 0, g_hx.side>>>(p, q, W, out);
        cudaEventRecord(g_hx.eB, g_hx.side);

        // main chain (R8/R13 order): w2prep first on stream 0, then the chain
        w2prep_kernel<<<(8*HP2*Ll + 255)/256, 256>>>(W);
        attcos_kernel<<<2*Bb, 256>>>(p, q);
        attvec_kernel<<<dim3(2*Bb, (Hh + 63)/64, 2), 256>>>(p, q);
        mpcos_kernel<<<dim3(2*Bb, 2, 2), 160>>>(p, q, out);

        cudaStreamWaitEvent(0, g_hx.eB, 0);
    } else {
        w2prep_kernel<<<(8*HP2*Ll + 255)/256, 256>>>(W);
        attcos_kernel<<<2*Bb, 256>>>(p, q);
        attvec_kernel<<<dim3(2*Bb, (Hh + 63)/64, 2), 256>>>(p, q);
        maxpool_kernel<<<dim3(Ll/2, Bb, 2), 256>>>(p, q, W, out);
        mpcos_kernel<<<dim3(2*Bb, 2, 2), 160>>>(p, q, out);
    }
}

// round 15
// speedup vs baseline: 1.7886x; 1.7886x over previous
#include <cuda_runtime.h>
#include <math.h>

#define Bb 32
#define Ss 64
#define Hh 300
#define HPAD 304
#define HP2 320
#define Ll 20
#define KC 16
#define NT (HPAD/KC)   // 19 tiles
#define KH 32
#define CH 160
#define PSIDE (Bb*Ss*CH)
#define EPSV 1e-8f
#define AVP 72   // attvec smem pitch (floats): 288B rows, 16B-aligned

typedef unsigned long long ull;

__device__ __forceinline__ void fma2(ull &d, ull a, ull b) {
    asm("fma.rn.f32x2 %0, %1, %2, %0;" : "+l"(d) : "l"(a), "l"(b));
}
__device__ __forceinline__ void mul2(ull &d, ull a, ull b) {
    asm("mul.rn.f32x2 %0, %1, %2;" : "=l"(d) : "l"(a), "l"(b));
}
__device__ __forceinline__ void add2(ull &d, ull a) {
    asm("add.rn.f32x2 %0, %0, %1;" : "+l"(d) : "l"(a));
}
__device__ __forceinline__ ull pk2(float x) {
    ull r; asm("mov.b64 %0, {%1, %1};" : "=l"(r) : "f"(x)); return r;
}
__device__ __forceinline__ float2 upk(ull v) {
    float2 r; asm("mov.b64 {%0, %1}, %2;" : "=f"(r.x), "=f"(r.y) : "l"(v)); return r;
}

// ---------------- scratch ----------------
__device__ float g_cos [2*Bb*Ss*Ss];
__device__ float g_rsum[2*Bb*Ss];
__device__ float g_csum[2*Bb*Ss];
__device__ float g_pvm [2*Bb*Ss*Hh];
__device__ float g_pvx [2*Bb*Ss*Hh];
__device__ float g_qvm [2*Bb*Ss*Hh];
__device__ float g_qvx [2*Bb*Ss*Hh];
__device__ float g_w2t [8*HP2*Ll];      // [wi][h][l], squared, zero-padded

// =========================================================================
// K0: transpose + square W -> g_w2t[wi][h][l]
// =========================================================================
__global__ void w2prep_kernel(const float* __restrict__ W)
{
    int idx = blockIdx.x * 256 + threadIdx.x;
    if (idx >= 8*HP2*Ll) return;
    int wi = idx / (HP2*Ll);
    int rem = idx - wi*(HP2*Ll);
    int h = rem / Ll, l = rem - h*Ll;
    float w = (h < Hh) ? W[(wi*Ll + l)*Hh + h] : 0.f;
    g_w2t[idx] = w * w;
}

// =========================================================================
// K1: unweighted cosine per (b,dir). 256 thr, 4x4 tile, FFMA2 inner loop.
// =========================================================================
__global__ void __launch_bounds__(256) attcos_kernel(const float* __restrict__ p,
                                                     const float* __restrict__ q)
{
    int bd = blockIdx.x;
    int d  = bd >> 5, b = bd & 31;
    int t  = threadIdx.x;
    int tr = t >> 4, tc = t & 15;
    int row_s = t >> 2, hq = t & 3;

    __shared__ __align__(16) float As[KC][64];
    __shared__ __align__(16) float Bs[KC][64];
    __shared__ float snorm[2][4][64];
    __shared__ float rn[2][64];
    __shared__ float red[16][64];

    const float* Pb = p + b*Ss*600 + d*Hh;
    const float* Qb = q + b*Ss*600 + d*Hh;

    ull acc2[4][2];
#pragma unroll
    for (int i = 0; i < 4; i++) { acc2[i][0] = 0ull; acc2[i][1] = 0ull; }
    float np2 = 0.f, nq2 = 0.f;

    for (int h0 = 0; h0 < HPAD; h0 += KC) {
        int h = h0 + hq*4;
        float4 pv, qv;
        if (h + 3 < Hh) {
            pv = *(const float4*)(Pb + row_s*600 + h);
            qv = *(const float4*)(Qb + row_s*600 + h);
        } else {
            float* pp = (float*)&pv; float* qq = (float*)&qv;
#pragma unroll
            for (int i = 0; i < 4; i++) {
                bool in = (h + i < Hh);
                pp[i] = in ? Pb[row_s*600 + h + i] : 0.f;
                qq[i] = in ? Qb[row_s*600 + h + i] : 0.f;
            }
        }
        As[hq*4+0][row_s] = pv.x; As[hq*4+1][row_s] = pv.y;
        As[hq*4+2][row_s] = pv.z; As[hq*4+3][row_s] = pv.w;
        Bs[hq*4+0][row_s] = qv.x; Bs[hq*4+1][row_s] = qv.y;
        Bs[hq*4+2][row_s] = qv.z; Bs[hq*4+3][row_s] = qv.w;
        np2 += pv.x*pv.x + pv.y*pv.y + pv.z*pv.z + pv.w*pv.w;
        nq2 += qv.x*qv.x + qv.y*qv.y + qv.z*qv.z + qv.w*qv.w;
        __syncthreads();
#pragma unroll
        for (int k = 0; k < KC; k++) {
            float4 a = *(const float4*)(&As[k][tr*4]);
            ulonglong2 bq = *(const ulonglong2*)(&Bs[k][tc*4]);
            ull a0 = pk2(a.x), a1 = pk2(a.y), a2 = pk2(a.z), a3 = pk2(a.w);
            fma2(acc2[0][0], a0, bq.x); fma2(acc2[0][1], a0, bq.y);
            fma2(acc2[1][0], a1, bq.x); fma2(acc2[1][1], a1, bq.y);
            fma2(acc2[2][0], a2, bq.x); fma2(acc2[2][1], a2, bq.y);
            fma2(acc2[3][0], a3, bq.x); fma2(acc2[3][1], a3, bq.y);
        }
        __syncthreads();
    }

    snorm[0][hq][row_s] = np2;
    snorm[1][hq][row_s] = nq2;
    __syncthreads();
    if (t < 64) {
        rn[0][t] = 1.f / sqrtf(snorm[0][0][t] + snorm[0][1][t] + snorm[0][2][t] + snorm[0][3][t]);
        rn[1][t] = 1.f / sqrtf(snorm[1][0][t] + snorm[1][1][t] + snorm[1][2][t] + snorm[1][3][t]);
    }
    __syncthreads();

    float rp[4], rq[4];
#pragma unroll
    for (int i = 0; i < 4; i++) rp[i] = rn[0][tr*4+i];
#pragma unroll
    for (int j = 0; j < 4; j++) rq[j] = rn[1][tc*4+j];

    float* gc = g_cos + bd*(Ss*Ss);
    float rowsum[4], colsum[4];
#pragma unroll
    for (int i = 0; i < 4; i++) rowsum[i] = 0.f;
#pragma unroll
    for (int j = 0; j < 4; j++) colsum[j] = 0.f;

#pragma unroll
    for (int i = 0; i < 4; i++) {
        float2 c0 = upk(acc2[i][0]);
        float2 c1 = upk(acc2[i][1]);
        float c[4] = {c0.x, c0.y, c1.x, c1.y};
#pragma unroll
        for (int j = 0; j < 4; j++) {
            c[j] *= rp[i] * rq[j];
            rowsum[i] += c[j];
            colsum[j] += c[j];
        }
        *(float4*)(gc + (tr*4+i)*64 + tc*4) = make_float4(c[0], c[1], c[2], c[3]);
    }

#pragma unroll
    for (int i = 0; i < 4; i++) red[tc][tr*4+i] = rowsum[i];
    __syncthreads();
    if (t < 64) {
        float s = 0.f;
#pragma unroll
        for (int g = 0; g < 16; g++) s += red[g][t];
        g_rsum[bd*Ss + t] = s;
    }
    __syncthreads();
#pragma unroll
    for (int j = 0; j < 4; j++) red[tr][tc*4+j] = colsum[j];
    __syncthreads();
    if (t < 64) {
        float s = 0.f;
#pragma unroll
        for (int g = 0; g < 16; g++) s += red[g][t];
        g_csum[bd*Ss + t] = s;
    }
}

// =========================================================================
// K2: attentive vectors (mean + max fused), packed f32x2 mul/add.
// __launch_bounds__(256,4): cap regs at 64.
// =========================================================================
__global__ void __launch_bounds__(256, 4) attvec_kernel(const float* __restrict__ p,
                                                        const float* __restrict__ q)
{
    int bd   = blockIdx.x;
    int d    = bd >> 5, b = bd & 31;
    int h0   = blockIdx.y * 64;
    int side = blockIdx.z;
    int t    = threadIdx.x;
    int ty   = t >> 4, tx = t & 15;

    __shared__ __align__(16) float As[64][AVP];
    __shared__ __align__(16) float Bs[64][AVP];

    const float* gc = g_cos + bd*(Ss*Ss);
    const float* M  = (side ? q : p) + b*Ss*600 + d*Hh;

    for (int idx = t; idx < 4096; idx += 256) {
        int row = idx >> 6, col = idx & 63;
        float cv = gc[row*64 + col];              // always coalesced
        if (side) As[col][row] = cv;              // transposed write
        else      As[row][col] = cv;
        int h = h0 + col;
        Bs[row][col] = (h < Hh) ? M[row*600 + h] : 0.f;
    }
    __syncthreads();

    ull accM2[4][2];
    float accX[4][4];
#pragma unroll
    for (int i = 0; i < 4; i++) {
        accM2[i][0] = 0ull; accM2[i][1] = 0ull;
#pragma unroll
        for (int j = 0; j < 4; j++) accX[i][j] = -INFINITY;
    }

    for (int k = 0; k < 64; k++) {
        float4 a = *(const float4*)(&As[k][ty*4]);
        ulonglong2 bq = *(const ulonglong2*)(&Bs[k][tx*4]);
        ull a2[4] = {pk2(a.x), pk2(a.y), pk2(a.z), pk2(a.w)};
#pragma unroll
        for (int i = 0; i < 4; i++) {
            ull pr0, pr1;
            mul2(pr0, a2[i], bq.x);
            mul2(pr1, a2[i], bq.y);
            add2(accM2[i][0], pr0);
            add2(accM2[i][1], pr1);
            float2 f0 = upk(pr0), f1 = upk(pr1);
            accX[i][0] = fmaxf(accX[i][0], f0.x);
            accX[i][1] = fmaxf(accX[i][1], f0.y);
            accX[i][2] = fmaxf(accX[i][2], f1.x);
            accX[i][3] = fmaxf(accX[i][3], f1.y);
        }
    }

    float* vm = (side ? g_qvm : g_pvm) + bd*Ss*Hh;
    float* vx = (side ? g_qvx : g_pvx) + bd*Ss*Hh;
    const float* den = (side ? g_rsum : g_csum) + bd*Ss;

#pragma unroll
    for (int i = 0; i < 4; i++) {
        int r = ty*4 + i;
        float dn = den[r];
        float2 m0 = upk(accM2[i][0]);
        float2 m1 = upk(accM2[i][1]);
        float mv[4] = {m0.x, m0.y, m1.x, m1.y};
#pragma unroll
        for (int j = 0; j < 4; j++) {
            int h = h0 + tx*4 + j;
            if (h < Hh) {
                vm[r*Hh + h] = mv[j] / dn;
                vx[r*Hh + h] = accX[i][j];
            }
        }
    }
}

// =========================================================================
// K3: maxpool, 2 l per block, 128 thr, DOUBLE-BUFFERED smem tiles:
// one barrier per tile instead of two; store targets the idle buffer
// while compute reads the other. Per thread 8 rows x 4 cols per l.
// =========================================================================
__global__ void __launch_bounds__(128) maxpool_kernel(const float* __restrict__ p,
                                                      const float* __restrict__ q,
                                                      const float* __restrict__ W,
                                                      float* __restrict__ out)
{
    int lp = blockIdx.x;
    int b  = blockIdx.y, d = blockIdx.z;
    int t  = threadIdx.x;
    int tr = t >> 4;
    int tc = t & 15;
    int row_s = t >> 1, seg = t & 1;

    __shared__ __align__(16) ull   Ap[2][KC][64];
    __shared__ __align__(16) float Bs[2][2][KC][64];   // [buf][l][k][col]
    __shared__ float ws2[2][HPAD];
    __shared__ float snorm[2][2][2][64];
    __shared__ float rn[2][2][64];
    __shared__ float red[16][64];

    const float* w0r = W + ((2 + d)*Ll + lp*2 + 0)*Hh;
    const float* w1r = W + ((2 + d)*Ll + lp*2 + 1)*Hh;
    for (int h = t; h < HPAD; h += 128) {
        float a = (h < Hh) ? w0r[h] : 0.f;
        float c = (h < Hh) ? w1r[h] : 0.f;
        ws2[0][h] = a * a;
        ws2[1][h] = c * c;
    }

    const float* Pb = p + b*Ss*600 + d*Hh;
    const float* Qb = q + b*Ss*600 + d*Hh;

    float pv[8], qv[8];
    float np2[2] = {0.f, 0.f}, nq2[2] = {0.f, 0.f};

    auto load_tile = [&](int h0n) {
#pragma unroll
        for (int c4 = 0; c4 < 2; c4++) {
            int h = h0n + seg*8 + c4*4;
            float4 pvv, qvv;
            if (h + 3 < Hh) {
                pvv = *(const float4*)(Pb + row_s*600 + h);
                qvv = *(const float4*)(Qb + row_s*600 + h);
            } else {
                float* pp = (float*)&pvv; float* qq = (float*)&qvv;
#pragma unroll
                for (int i = 0; i < 4; i++) {
                    bool in = (h + i < Hh);
                    pp[i] = in ? Pb[row_s*600 + h + i] : 0.f;
                    qq[i] = in ? Qb[row_s*600 + h + i] : 0.f;
                }
            }
            pv[c4*4+0] = pvv.x; pv[c4*4+1] = pvv.y; pv[c4*4+2] = pvv.z; pv[c4*4+3] = pvv.w;
            qv[c4*4+0] = qvv.x; qv[c4*4+1] = qvv.y; qv[c4*4+2] = qvv.z; qv[c4*4+3] = qvv.w;
        }
    };
    auto store_tile = [&](int buf, int h0n) {
        int hb = h0n + seg*8;
#pragma unroll
        for (int j = 0; j < 8; j++) {
            int kk = seg*8 + j;
            Ap[buf][kk][row_s] = pk2(pv[j]);
            float wa = ws2[0][hb + j], wb = ws2[1][hb + j];
            Bs[buf][0][kk][row_s] = qv[j] * wa;
            Bs[buf][1][kk][row_s] = qv[j] * wb;
            np2[0] += pv[j]*pv[j]*wa;  np2[1] += pv[j]*pv[j]*wb;
            nq2[0] += qv[j]*qv[j]*wa;  nq2[1] += qv[j]*qv[j]*wb;
        }
    };

    load_tile(0);                   // global prefetch tile 0 (regs)
    __syncthreads();                // ws2 ready
    store_tile(0, 0);
    __syncthreads();                // buffer 0 ready

    ull acc2[2][8][2];
#pragma unroll
    for (int l = 0; l < 2; l++)
#pragma unroll
        for (int i = 0; i < 8; i++)
#pragma unroll
            for (int j = 0; j < 2; j++) acc2[l][i][j] = 0ull;

    for (int it = 0; it < NT; it++) {
        int cur = it & 1;
        if (it + 1 < NT) load_tile((it + 1)*KC);      // global prefetch
#pragma unroll
        for (int k = 0; k < KC; k++) {
            ull av2[8];
            ulonglong2 a01 = *(const ulonglong2*)(&Ap[cur][k][tr*8+0]);
            ulonglong2 a23 = *(const ulonglong2*)(&Ap[cur][k][tr*8+2]);
            ulonglong2 a45 = *(const ulonglong2*)(&Ap[cur][k][tr*8+4]);
            ulonglong2 a67 = *(const ulonglong2*)(&Ap[cur][k][tr*8+6]);
            av2[0]=a01.x; av2[1]=a01.y; av2[2]=a23.x; av2[3]=a23.y;
            av2[4]=a45.x; av2[5]=a45.y; av2[6]=a67.x; av2[7]=a67.y;
            ulonglong2 b0 = *(const ulonglong2*)(&Bs[cur][0][k][tc*4]);
            ulonglong2 b1 = *(const ulonglong2*)(&Bs[cur][1][k][tc*4]);
#pragma unroll
            for (int i = 0; i < 8; i++) {
                fma2(acc2[0][i][0], av2[i], b0.x);
                fma2(acc2[0][i][1], av2[i], b0.y);
                fma2(acc2[1][i][0], av2[i], b1.x);
                fma2(acc2[1][i][1], av2[i], b1.y);
            }
        }
        if (it + 1 < NT) store_tile((it + 1) & 1, (it + 1)*KC);  // idle buffer
        __syncthreads();   // next buffer visible; current buffer free for it+2's store
    }

#pragma unroll
    for (int l = 0; l < 2; l++) {
        snorm[l][0][seg][row_s] = np2[l];
        snorm[l][1][seg][row_s] = nq2[l];
    }
    __syncthreads();
    if (t < 64) {
#pragma unroll
        for (int l = 0; l < 2; l++) {
            rn[l][0][t] = sqrtf(snorm[l][0][0][t] + snorm[l][0][1][t]);
            rn[l][1][t] = sqrtf(snorm[l][1][0][t] + snorm[l][1][1][t]);
        }
    }
    __syncthreads();

#pragma unroll
    for (int l = 0; l < 2; l++) {
        float npv[8], nqv[4], rmax[8], cmax[4];
#pragma unroll
        for (int i = 0; i < 8; i++) { npv[i] = rn[l][0][tr*8+i]; rmax[i] = -INFINITY; }
#pragma unroll
        for (int j = 0; j < 4; j++) { nqv[j] = rn[l][1][tc*4+j]; cmax[j] = -INFINITY; }

#pragma unroll
        for (int i = 0; i < 8; i++) {
            float2 c0 = upk(acc2[l][i][0]);
            float2 c1 = upk(acc2[l][i][1]);
            float cf[4] = {c0.x, c0.y, c1.x, c1.y};
#pragma unroll
            for (int j = 0; j < 4; j++) {
                float c = cf[j] / fmaxf(npv[i]*nqv[j], EPSV);
                rmax[i] = fmaxf(rmax[i], c);
                cmax[j] = fmaxf(cmax[j], c);
            }
        }

        int ch = (2 + d)*Ll + lp*2 + l;
#pragma unroll
        for (int i = 0; i < 8; i++) red[tc][tr*8+i] = rmax[i];
        __syncthreads();
        if (t < 64) {
            float m = -INFINITY;
#pragma unroll
            for (int g = 0; g < 16; g++) m = fmaxf(m, red[g][t]);
            out[(b*Ss + t)*CH + ch] = m;
        }
        __syncthreads();
#pragma unroll
        for (int j = 0; j < 4; j++) red[tr][tc*4+j] = cmax[j];
        __syncthreads();
        if (t < 64) {
            float m = -INFINITY;
#pragma unroll
            for (int g = 0; g < 8; g++) m = fmaxf(m, red[g][t]);
            out[PSIDE + (b*Ss + t)*CH + ch] = m;
        }
        __syncthreads();
    }
}

// =========================================================================
// K4: mp_cos epilogue. Block = (b, s-half, dir, side): 256 blocks, 160 thr.
// =========================================================================
__global__ void __launch_bounds__(160) mpcos_kernel(const float* __restrict__ p,
                                                    const float* __restrict__ q,
                                                    float* __restrict__ out)
{
    int b    = blockIdx.x >> 1;
    int sh   = blockIdx.x & 1;
    int dir  = blockIdx.y;
    int side = blockIdx.z;
    int t    = threadIdx.x;
    int s    = t & 31;
    int lg   = t >> 5;
    int l0   = lg * 4;
    int bd   = dir*Bb + b;
    int sg   = sh*32 + s;

    __shared__ float xt [KH][33];
    __shared__ float ymt[KH][33];
    __shared__ float yxt[KH][33];
    __shared__ float yfs[KH];
    __shared__ __align__(16) float w2s[3][KH][20];

    const float* Xb  = (side ? q : p) + (b*Ss + sh*32)*600 + dir*Hh;
    const float* Yfb = (side ? p : q) + (b*Ss + (dir ? 0 : (Ss-1)))*600 + dir*Hh;
    const float* Ymb = (side ? g_pvm : g_qvm) + (bd*Ss + sh*32)*Hh;
    const float* Yxb = (side ? g_pvx : g_qvx) + (bd*Ss + sh*32)*Hh;
    const int wi0 = dir, wi1 = 4 + dir, wi2 = 6 + dir;

    ull aF[2][3], aM[2][3], aX[2][3];
#pragma unroll
    for (int pr = 0; pr < 2; pr++)
#pragma unroll
        for (int m = 0; m < 3; m++) { aF[pr][m] = 0ull; aM[pr][m] = 0ull; aX[pr][m] = 0ull; }

    for (int h0 = 0; h0 < HP2; h0 += KH) {
        for (int idx = t; idx < 256; idx += 160) {
            int s_ = idx >> 3, qd = idx & 7;
            int h = h0 + qd*4;
            float4 xv, mv, vv;
            if (h + 3 < Hh) {
                xv = *(const float4*)(Xb  + s_*600 + h);
                mv = *(const float4*)(Ymb + s_*Hh  + h);
                vv = *(const float4*)(Yxb + s_*Hh  + h);
            } else {
                float* xp = (float*)&xv; float* mp2 = (float*)&mv; float* vp = (float*)&vv;
#pragma unroll
                for (int i = 0; i < 4; i++) {
                    bool in = (h + i < Hh);
                    xp[i]  = in ? Xb [s_*600 + h + i] : 0.f;
                    mp2[i] = in ? Ymb[s_*Hh  + h + i] : 0.f;
                    vp[i]  = in ? Yxb[s_*Hh  + h + i] : 0.f;
                }
            }
            float* xp = (float*)&xv; float* mp2 = (float*)&mv; float* vp = (float*)&vv;
#pragma unroll
            for (int i = 0; i < 4; i++) {
                xt [qd*4+i][s_] = xp[i];
                ymt[qd*4+i][s_] = mp2[i];
                yxt[qd*4+i][s_] = vp[i];
            }
        }
        if (t < KH) {
            int h = h0 + t;
            yfs[t] = (h < Hh) ? Yfb[h] : 0.f;
        }
        for (int idx = t; idx < 480; idx += 160) {
            int stg = idx / 160;
            int rem = idx - stg*160;
            int kk = rem / 5, lq2 = rem - kk*5;
            int wi = (stg == 0) ? wi0 : (stg == 1 ? wi1 : wi2);
            float4 wv = *(const float4*)(g_w2t + (wi*HP2 + h0 + kk)*Ll + lq2*4);
            *(float4*)(&w2s[stg][kk][lq2*4]) = wv;
        }
        __syncthreads();

#pragma unroll
        for (int kk = 0; kk < KH; kk++) {
            float x   = xt [kk][s];
            float ymv = ymt[kk][s];
            float yxv = yxt[kk][s];
            float yfv = yfs[kk];

            ull XX = pk2(x*x);
            ull PF = pk2(x*yfv);
            ull F2 = pk2(yfv*yfv);
            ull PM = pk2(x*ymv);
            ull M2 = pk2(ymv*ymv);
            ull PX = pk2(x*yxv);
            ull X2 = pk2(yxv*yxv);

            const ull* wf = (const ull*)&w2s[0][kk][l0];
            const ull* wm = (const ull*)&w2s[1][kk][l0];
            const ull* wx = (const ull*)&w2s[2][kk][l0];
#pragma unroll
            for (int pr = 0; pr < 2; pr++) {
                ull wfp = wf[pr], wmp = wm[pr], wxp = wx[pr];
                fma2(aF[pr][0], XX, wfp); fma2(aF[pr][1], PF, wfp); fma2(aF[pr][2], F2, wfp);
                fma2(aM[pr][0], XX, wmp); fma2(aM[pr][1], PM, wmp); fma2(aM[pr][2], M2, wmp);
                fma2(aX[pr][0], XX, wxp); fma2(aX[pr][1], PX, wxp); fma2(aX[pr][2], X2, wxp);
            }
        }
        __syncthreads();
    }

    float* ob = out + side*PSIDE + (b*Ss + sg)*CH;
#pragma unroll
    for (int pr = 0; pr < 2; pr++) {
        float2 nxF = upk(aF[pr][0]), numF = upk(aF[pr][1]), nyF = upk(aF[pr][2]);
        float2 nxM = upk(aM[pr][0]), numM = upk(aM[pr][1]), nyM = upk(aM[pr][2]);
        float2 nxX = upk(aX[pr][0]), numX = upk(aX[pr][1]), nyX = upk(aX[pr][2]);
#pragma unroll
        for (int hl = 0; hl < 2; hl++) {
            int l = l0 + pr*2 + hl;
            float nxf = hl ? nxF.y : nxF.x, nuf = hl ? numF.y : numF.x, nyf = hl ? nyF.y : nyF.x;
            float nxm = hl ? nxM.y : nxM.x, num = hl ? numM.y : numM.x, nym = hl ? nyM.y : nyM.x;
            float nxx = hl ? nxX.y : nxX.x, nux = hl ? numX.y : numX.x, nyx = hl ? nyX.y : nyX.x;
            ob[  0 + dir*Ll + l] = nuf / fmaxf(sqrtf(nxf)*sqrtf(nyf), EPSV);
            ob[ 80 + dir*Ll + l] = num / fmaxf(sqrtf(nxm)*sqrtf(nym), EPSV);
            ob[120 + dir*Ll + l] = nux / fmaxf(sqrtf(nxx)*sqrtf(nyx), EPSV);
        }
    }
}

// =========================================================================
// Fork/join plumbing (static-init; no device allocations afterwards).
// =========================================================================
struct HxCtx {
    cudaStream_t side;
    cudaEvent_t  eA, eB;
    bool ok;
    HxCtx() : ok(false) {
        if (cudaStreamCreateWithFlags(&side, cudaStreamNonBlocking) != cudaSuccess) return;
        if (cudaEventCreateWithFlags(&eA, cudaEventDisableTiming) != cudaSuccess) return;
        if (cudaEventCreateWithFlags(&eB, cudaEventDisableTiming) != cudaSuccess) return;
        ok = true;
    }
};
static HxCtx g_hx;

extern "C" void kernel_launch(void* const* d_in, const int* in_sizes, int n_in,
                              void* d_out, int out_size) {
    const float* p = (const float*)d_in[0];
    const float* q = (const float*)d_in[1];
    const float* W = (const float*)d_in[2];
    float* out = (float*)d_out;

    if (g_hx.ok) {
        // fork: maxpool on side stream, independent of the attentive chain
        cudaEventRecord(g_hx.eA, 0);
        cudaStreamWaitEvent(g_hx.side, g_hx.eA, 0);
        maxpool_kernel<<<dim3(Ll/2, Bb, 2), 128, 0, g_hx.side>>>(p, q, W, out);
        cudaEventRecord(g_hx.eB, g_hx.side);

        // main chain (R13 order): w2prep first on stream 0, then the chain
        w2prep_kernel<<<(8*HP2*Ll + 255)/256, 256>>>(W);
        attcos_kernel<<<2*Bb, 256>>>(p, q);
        attvec_kernel<<<dim3(2*Bb, (Hh + 63)/64, 2), 256>>>(p, q);
        mpcos_kernel<<<dim3(2*Bb, 2, 2), 160>>>(p, q, out);

        cudaStreamWaitEvent(0, g_hx.eB, 0);
    } else {
        w2prep_kernel<<<(8*HP2*Ll + 255)/256, 256>>>(W);
        attcos_kernel<<<2*Bb, 256>>>(p, q);
        attvec_kernel<<<dim3(2*Bb, (Hh + 63)/64, 2), 256>>>(p, q);
        maxpool_kernel<<<dim3(Ll/2, Bb, 2), 128>>>(p, q, W, out);
        mpcos_kernel<<<dim3(2*Bb, 2, 2), 160>>>(p, q, out);
    }
}